// round 15
// baseline (speedup 1.0000x reference)
#include <cuda_runtime.h>
#include <cuda_fp16.h>
#include <cstdint>

// LSTM N=64, T=512, D=1024, H=1024, G=4096.
// Phase A: xW = x @ Wx + b  -- HMMA fp16, Wx 2-term split, x fp16 (128x64, proven).
// Phase B: persistent kernel, 128 CTAs x 512 threads, HMMA fp16 2-term split on Wh,
//          h single fp16 pre-fragmented, 8wk x 2wn warp tiles, producer dataflow sync.
// R15: lo-term accumulators in fp16 (frees 16 regs; lo is pre-scaled x2048 so f16
//      acc error ~2^-22 of total) + A-fragment double-buffering with the freed regs.

#define N_  64
#define T_  512
#define D_  1024
#define H_  1024
#define G_  4096
#define M_  (N_ * T_)
#define NCTA 128
#define INV2048 (1.0f / 2048.0f)

typedef unsigned long long ull;

// -------- device globals --------
static __device__ __align__(16) float  g_xw[(size_t)M_ * G_];          // 512 MB
static __device__ __align__(16) __half g_xh[(size_t)M_ * D_];          // 64 MB
static __device__ __align__(16) __half g_wxT[2ULL * G_ * D_];          // 16 MB
static __device__ __align__(16) __half g_whs[NCTA * 2 * 32 * 1024];    // 16 MB
// h fragments: [phase][k16 0..63][np 0..3][lane 0..31][8 fp16]
static __device__ __align__(16) __half g_hf[2][64][4][32][8];
// dataflow flags: one 128B line per CTA
static __device__ __align__(128) unsigned g_flags[NCTA * 32];

__device__ __forceinline__ float sigmoidf_(float x) { return 1.0f / (1.0f + __expf(-x)); }
__device__ __forceinline__ float fast_tanh(float x) {
    float ax = fabsf(x);
    float e = __expf(-2.0f * ax);
    float t = (1.0f - e) / (1.0f + e);
    return copysignf(t, x);
}

// -------- async copy --------
__device__ __forceinline__ void cp16(uint32_t s, const void* g) {
    asm volatile("cp.async.cg.shared.global [%0], [%1], 16;" :: "r"(s), "l"(g));
}
__device__ __forceinline__ void cp_commit() { asm volatile("cp.async.commit_group;"); }
template <int NN>
__device__ __forceinline__ void cp_wait() { asm volatile("cp.async.wait_group %0;" :: "n"(NN)); }

__device__ __forceinline__ uint32_t smem_u32(const void* p) {
    uint32_t a;
    asm("{ .reg .u64 t; cvta.to.shared.u64 t, %1; cvt.u32.u64 %0, t; }" : "=r"(a) : "l"(p));
    return a;
}

// -------- mma helpers --------
__device__ __forceinline__ void ldm4(uint32_t addr, uint32_t* r) {
    asm volatile("ldmatrix.sync.aligned.m8n8.x4.shared.b16 {%0,%1,%2,%3}, [%4];"
                 : "=r"(r[0]), "=r"(r[1]), "=r"(r[2]), "=r"(r[3]) : "r"(addr));
}
__device__ __forceinline__ void mma16816(float* d, const uint32_t* a, uint32_t b0, uint32_t b1) {
    asm volatile(
        "mma.sync.aligned.m16n8k16.row.col.f32.f16.f16.f32 "
        "{%0,%1,%2,%3}, {%4,%5,%6,%7}, {%8,%9}, {%0,%1,%2,%3};"
        : "+f"(d[0]), "+f"(d[1]), "+f"(d[2]), "+f"(d[3])
        : "r"(a[0]), "r"(a[1]), "r"(a[2]), "r"(a[3]), "r"(b0), "r"(b1));
}
// fp16-accumulator variant (lo term)
__device__ __forceinline__ void mma16816_h(uint32_t* d, const uint32_t* a, uint32_t b0, uint32_t b1) {
    asm volatile(
        "mma.sync.aligned.m16n8k16.row.col.f16.f16.f16.f16 "
        "{%0,%1}, {%2,%3,%4,%5}, {%6,%7}, {%0,%1};"
        : "+r"(d[0]), "+r"(d[1])
        : "r"(a[0]), "r"(a[1]), "r"(a[2]), "r"(a[3]), "r"(b0), "r"(b1));
}

// ---------------- merged prep kernels ----------------
__global__ void prep_xwx(const float* __restrict__ x, const float* __restrict__ Wx) {
    int bid = blockIdx.x;
    if (bid < 1024) {
        int k = bid;
        const float* src = Wx + (size_t)k * G_;
        for (int col = threadIdx.x; col < G_; col += 256) {
            float w = src[col];
            __half hi = __float2half_rn(w);
            __half lo = __float2half_rn((w - __half2float(hi)) * 2048.0f);
            g_wxT[(size_t)col * D_ + k]        = hi;
            g_wxT[(size_t)(G_ + col) * D_ + k] = lo;
        }
    } else {
        size_t i = ((size_t)(bid - 1024) * 256 + threadIdx.x) * 4;
        float4 v = *(const float4*)(x + i);
        __half h[4] = {__float2half_rn(v.x), __float2half_rn(v.y),
                       __float2half_rn(v.z), __float2half_rn(v.w)};
        *(uint2*)(g_xh + i) = *(uint2*)h;
    }
}

__global__ void prep_whh0(const float* __restrict__ Wh, const float* __restrict__ h0) {
    int bid = blockIdx.x;
    int tid = threadIdx.x;
    if (bid < NCTA) {
        int b = bid;
        int m = tid & 31;
        int g = m >> 3, j = m & 7;
        int col = g * 1024 + b * 8 + j;
        __half* dh = g_whs + ((size_t)(b * 2 + 0) * 32 + m) * 1024;
        __half* dl = g_whs + ((size_t)(b * 2 + 1) * 32 + m) * 1024;
        for (int k = tid >> 5; k < 1024; k += 8) {
            float w = Wh[(size_t)k * G_ + col];
            __half hi = __float2half_rn(w);
            __half lo = __float2half_rn((w - __half2float(hi)) * 2048.0f);
            dh[k] = hi;
            dl[k] = lo;
        }
    } else {
        int i = (bid - NCTA) * 256 + tid;
        if (i < N_ * H_) {
            int n = i >> 10, k = i & 1023;
            int lane = (n & 7) * 4 + ((k & 7) >> 1);
            int idx8 = ((n >> 3) & 1) * 4 + (((k >> 3) & 1) * 2 + (k & 1));
            g_hf[0][k >> 4][n >> 4][lane][idx8] = __float2half_rn(h0[i]);
        }
        if (i < NCTA * 32) g_flags[i] = 0u;
    }
}

// ---------------- Phase A: xW = x @ Wx + b via HMMA (R9-proven) ----------------
#define PA_PITCH 144
#define PA_ABUF(i) ((i) * 18432)
#define PA_BBUF(i) (36864 + (i) * 18432)
#define PA_SMEM 73728

__global__ __launch_bounds__(256, 2)
void gemm_xw_hmma(const float* __restrict__ bias) {
    extern __shared__ char smem[];
    const uint32_t sb = smem_u32(smem);

    const int tid  = threadIdx.x;
    const int wid  = tid >> 5;
    const int lane = tid & 31;
    const int bx = blockIdx.x;
    const int by = blockIdx.y;
    const int m0 = by * 128;
    const int n0 = bx * 64;

    const char* Asrc = (const char*)g_xh + (size_t)m0 * 2048;
    const char* Bsrc = (const char*)g_wxT;

    const int wm = wid >> 1;
    const int wn = wid & 1;

    auto issue = [&](int kt, int bi) {
        const int k0b = kt * 128;
        const uint32_t ab = sb + PA_ABUF(bi);
        const uint32_t bb = sb + PA_BBUF(bi);
        #pragma unroll
        for (int i = 0; i < 4; i++) {
            int p = tid + 256 * i;
            int row = p >> 3, seg = p & 7;
            cp16(ab + row * PA_PITCH + seg * 16,
                 Asrc + (size_t)row * 2048 + k0b + seg * 16);
        }
        #pragma unroll
        for (int i = 0; i < 4; i++) {
            int p = tid + 256 * i;
            int row = p >> 3, seg = p & 7;
            int term = row >> 6, n = row & 63;
            cp16(bb + row * PA_PITCH + seg * 16,
                 Bsrc + ((size_t)term * G_ + n0 + n) * 2048 + k0b + seg * 16);
        }
    };

    float acc[2][2][4][4];
    #pragma unroll
    for (int s = 0; s < 2; s++)
        #pragma unroll
        for (int mi = 0; mi < 2; mi++)
            #pragma unroll
            for (int j = 0; j < 4; j++)
                #pragma unroll
                for (int i = 0; i < 4; i++) acc[s][mi][j][i] = 0.0f;

    const uint32_t lrow = (uint32_t)(lane & 15);
    const uint32_t lseg = (uint32_t)(lane >> 4) * 16;

    issue(0, 0);
    cp_commit();

    for (int kt = 0; kt < 16; kt++) {
        if (kt < 15) { issue(kt + 1, (kt + 1) & 1); cp_commit(); cp_wait<1>(); }
        else         { cp_wait<0>(); }
        __syncthreads();

        const uint32_t ab = sb + PA_ABUF(kt & 1);
        const uint32_t bb = sb + PA_BBUF(kt & 1);
        const uint32_t aA0 = ab + (wm * 32 + lrow) * PA_PITCH + lseg;
        const uint32_t aA1 = aA0 + 16 * PA_PITCH;

        #pragma unroll
        for (int k16 = 0; k16 < 4; k16++) {
            uint32_t af[2][4];
            ldm4(aA0 + k16 * 32, af[0]);
            ldm4(aA1 + k16 * 32, af[1]);
            #pragma unroll
            for (int s = 0; s < 2; s++) {
                #pragma unroll
                for (int tau = 0; tau < 2; tau++) {
                    uint32_t bf[4];
                    uint32_t baddr = bb + (s * 64 + wn * 32 + tau * 16 + lrow) * PA_PITCH
                                        + lseg + k16 * 32;
                    ldm4(baddr, bf);
                    mma16816(acc[s][0][tau * 2 + 0], af[0], bf[0], bf[2]);
                    mma16816(acc[s][0][tau * 2 + 1], af[0], bf[1], bf[3]);
                    mma16816(acc[s][1][tau * 2 + 0], af[1], bf[0], bf[2]);
                    mma16816(acc[s][1][tau * 2 + 1], af[1], bf[1], bf[3]);
                }
            }
        }
        __syncthreads();
    }

    const int erow = lane >> 2;
    const int ecol = (lane & 3) * 2;
    #pragma unroll
    for (int mi = 0; mi < 2; mi++) {
        #pragma unroll
        for (int j = 0; j < 4; j++) {
            int col = n0 + wn * 32 + j * 8 + ecol;
            float2 bb2 = *(const float2*)(bias + col);
            int row = m0 + wm * 32 + mi * 16 + erow;
            float c0 = fmaf(acc[1][mi][j][0], INV2048, acc[0][mi][j][0]) + bb2.x;
            float c1 = fmaf(acc[1][mi][j][1], INV2048, acc[0][mi][j][1]) + bb2.y;
            float c2 = fmaf(acc[1][mi][j][2], INV2048, acc[0][mi][j][2]) + bb2.x;
            float c3 = fmaf(acc[1][mi][j][3], INV2048, acc[0][mi][j][3]) + bb2.y;
            *(float2*)(g_xw + (size_t)row * G_ + col)       = make_float2(c0, c1);
            *(float2*)(g_xw + (size_t)(row + 8) * G_ + col) = make_float2(c2, c3);
        }
    }
}

// ---------------- Phase B SMEM ----------------
#define WHS_PITCH 2064
#define SMP_OFF   132096
#define SMEM_TOT  (132096 + 67584)   // 199680

// 8 hi (fp32 acc) + 8 lo (fp16 acc) MMAs for one k16 step
#define PB_COMPUTE(A, c0, c1)                                \
    do {                                                     \
        mma16816(dh[0][0],   (A),      (c0).x, (c0).y);      \
        mma16816(dh[0][1],   (A),      (c0).z, (c0).w);      \
        mma16816(dh[0][2],   (A),      (c1).x, (c1).y);      \
        mma16816(dh[0][3],   (A),      (c1).z, (c1).w);      \
        mma16816(dh[1][0],   (A) + 4,  (c0).x, (c0).y);      \
        mma16816(dh[1][1],   (A) + 4,  (c0).z, (c0).w);      \
        mma16816(dh[1][2],   (A) + 4,  (c1).x, (c1).y);      \
        mma16816(dh[1][3],   (A) + 4,  (c1).z, (c1).w);      \
        mma16816_h(dl[0][0], (A) + 8,  (c0).x, (c0).y);      \
        mma16816_h(dl[0][1], (A) + 8,  (c0).z, (c0).w);      \
        mma16816_h(dl[0][2], (A) + 8,  (c1).x, (c1).y);      \
        mma16816_h(dl[0][3], (A) + 8,  (c1).z, (c1).w);      \
        mma16816_h(dl[1][0], (A) + 12, (c0).x, (c0).y);      \
        mma16816_h(dl[1][1], (A) + 12, (c0).z, (c0).w);      \
        mma16816_h(dl[1][2], (A) + 12, (c1).x, (c1).y);      \
        mma16816_h(dl[1][3], (A) + 12, (c1).z, (c1).w);      \
    } while (0)

#define PB_LDA(kk, A)                                 \
    do {                                              \
        ldm4(aHi0 + (kk) * 32, (A));                  \
        ldm4(aHi1 + (kk) * 32, (A) + 4);              \
        ldm4(aLo0 + (kk) * 32, (A) + 8);              \
        ldm4(aLo1 + (kk) * 32, (A) + 12);             \
    } while (0)

__global__ __launch_bounds__(512, 1)
void lstm_mma(float* __restrict__ out) {
    extern __shared__ char smem[];
    const uint32_t sb = smem_u32(smem);
    float* sm_p = (float*)(smem + SMP_OFF);   // [8][32][66]

    const int tid  = threadIdx.x;
    const int wid  = tid >> 5;
    const int lane = tid & 31;
    const int b    = blockIdx.x;

    // ---- one-time: Wh slice -> padded SMEM ----
    {
        const char* src = (const char*)(g_whs + (size_t)b * 2 * 32 * 1024);
        for (int p = tid; p < 8192; p += 512) {
            int row = p >> 7;
            int seg = p & 127;
            cp16(sb + row * WHS_PITCH + seg * 16, src + row * 2048 + seg * 16);
        }
        cp_commit();
        cp_wait<0>();
        __syncthreads();
    }

    const int wk = wid & 7;
    const int wn = wid >> 3;          // 0..1
    const int kk0 = wk * 8;
    const int np0 = wn * 2;

    const uint32_t aBase = sb + (uint32_t)(lane & 15) * WHS_PITCH + (uint32_t)(lane >> 4) * 16;
    const uint32_t aHi0 = aBase;
    const uint32_t aHi1 = aBase + 16 * WHS_PITCH;
    const uint32_t aLo0 = aBase + 32 * WHS_PITCH;
    const uint32_t aLo1 = aBase + 48 * WHS_PITCH;

    const int prow = lane >> 2;
    const int pcol = (lane & 3) * 2;

    const int en = tid >> 3;
    const int ej = tid & 7;
    const int jg = b * 8 + ej;
    float cc = 0.0f;
    const int wlane = (en & 7) * 4 + ((jg & 7) >> 1);
    const int widx8 = ((en >> 3) & 1) * 4 + (((jg >> 3) & 1) * 2 + (jg & 1));
    __half* hwp = &g_hf[0][jg >> 4][en >> 4][wlane][widx8];
    const size_t hphase_stride = (size_t)64 * 4 * 32 * 8;

    unsigned* myflag = &g_flags[b * 32];
    const unsigned* prodflag = &g_flags[(2 * kk0 + (lane & 15)) * 32];

    for (int t = 0; t < T_; t++) {
        const int p = t & 1, q = p ^ 1;
        const uint4* bPtr = (const uint4*)&g_hf[p][0][0][0][0] + lane;

        // ---- prefetch xw pre-activations (flag-independent) ----
        float xw[4];
        {
            const float* xp = g_xw + ((size_t)en * T_ + t) * G_ + jg;
            #pragma unroll
            for (int g = 0; g < 4; g++) xw[g] = xp[g * 1024];
        }

        // ---- dataflow wait: this warp's 16 producers ----
        {
            const unsigned need = (unsigned)t;
            unsigned v;
            for (;;) {
                asm volatile("ld.acquire.gpu.global.u32 %0, [%1];"
                             : "=r"(v) : "l"(prodflag) : "memory");
                if (__all_sync(0xffffffffu, v >= need)) break;
            }
        }

        float    dh[2][4][4];
        uint32_t dl[2][4][2];
        #pragma unroll
        for (int m = 0; m < 2; m++)
            #pragma unroll
            for (int j = 0; j < 4; j++) {
                dh[m][j][0] = 0.0f; dh[m][j][1] = 0.0f;
                dh[m][j][2] = 0.0f; dh[m][j][3] = 0.0f;
                dl[m][j][0] = 0u;   dl[m][j][1] = 0u;
            }

        // A + B double-buffered pipeline
        uint4 b0A, b1A, b0B, b1B;
        uint32_t aA[16], aB[16];
        b0A = bPtr[((kk0 + 0) * 4 + np0) * 32];
        b1A = bPtr[((kk0 + 0) * 4 + np0 + 1) * 32];
        PB_LDA(kk0, aA);

        #pragma unroll
        for (int su = 0; su < 8; su += 2) {
            {
                int kk = kk0 + su + 1;
                b0B = bPtr[(kk * 4 + np0) * 32];
                b1B = bPtr[(kk * 4 + np0 + 1) * 32];
                PB_LDA(kk, aB);
            }
            PB_COMPUTE(aA, b0A, b1A);
            if (su + 2 < 8) {
                int kk = kk0 + su + 2;
                b0A = bPtr[(kk * 4 + np0) * 32];
                b1A = bPtr[(kk * 4 + np0 + 1) * 32];
                PB_LDA(kk, aA);
            }
            PB_COMPUTE(aB, b0B, b1B);
        }

        // ---- combine hi + lo/2048 (lo in fp16 pairs), store partials ----
        #pragma unroll
        for (int m = 0; m < 2; m++) {
            #pragma unroll
            for (int j = 0; j < 4; j++) {
                __half2 l0 = *(__half2*)&dl[m][j][0];   // (r,c),(r,c+1)
                __half2 l1 = *(__half2*)&dl[m][j][1];   // (r+8,c),(r+8,c+1)
                float f0 = fmaf(__low2float(l0),  INV2048, dh[m][j][0]);
                float f1 = fmaf(__high2float(l0), INV2048, dh[m][j][1]);
                float f2 = fmaf(__low2float(l1),  INV2048, dh[m][j][2]);
                float f3 = fmaf(__high2float(l1), INV2048, dh[m][j][3]);
                float* qp = sm_p + (wk * 32 + m * 16 + prow) * 66 + wn * 32 + j * 8 + pcol;
                *(float2*)qp            = make_float2(f0, f1);
                *(float2*)(qp + 8 * 66) = make_float2(f2, f3);
            }
        }
        __syncthreads();

        // ---- gates + state update (8-way partial reduction) ----
        {
            float a[4];
            #pragma unroll
            for (int g = 0; g < 4; g++) {
                int row = g * 8 + ej;
                float s0 = sm_p[(0 * 32 + row) * 66 + en] + sm_p[(1 * 32 + row) * 66 + en];
                float s1 = sm_p[(2 * 32 + row) * 66 + en] + sm_p[(3 * 32 + row) * 66 + en];
                float s2 = sm_p[(4 * 32 + row) * 66 + en] + sm_p[(5 * 32 + row) * 66 + en];
                float s3 = sm_p[(6 * 32 + row) * 66 + en] + sm_p[(7 * 32 + row) * 66 + en];
                a[g] = (s0 + s1) + (s2 + s3) + xw[g];
            }
            float ig = sigmoidf_(a[0]), fg = sigmoidf_(a[1]), og = sigmoidf_(a[2]);
            float gg = fast_tanh(a[3]);
            cc = fg * cc + ig * gg;
            float h = og * fast_tanh(cc);
            out[((size_t)en * T_ + t) * H_ + jg] = h;
            hwp[(size_t)q * hphase_stride] = __float2half_rn(h);
        }

        // ---- publish ----
        __syncthreads();
        if (tid == 0) {
            asm volatile("st.release.gpu.global.u32 [%0], %1;"
                         :: "l"(myflag), "r"((unsigned)(t + 1)) : "memory");
        }
    }
}

// ---------------- launch ----------------
extern "C" void kernel_launch(void* const* d_in, const int* in_sizes, int n_in,
                              void* d_out, int out_size) {
    const float* x  = (const float*)d_in[0];   // (N, T, D)
    const float* h0 = (const float*)d_in[1];   // (N, H)
    const float* Wx = (const float*)d_in[2];   // (D, 4H)
    const float* Wh = (const float*)d_in[3];   // (H, 4H)
    const float* b  = (const float*)d_in[4];   // (4H,)
    float* out = (float*)d_out;                // (N, T, H)

    prep_xwx<<<1024 + (int)((size_t)M_ * D_ / 1024), 256>>>(x, Wx);
    prep_whh0<<<NCTA + (N_ * H_ + 255) / 256, 256>>>(Wh, h0);

    cudaFuncSetAttribute(gemm_xw_hmma, cudaFuncAttributeMaxDynamicSharedMemorySize, PA_SMEM);
    dim3 gridA(G_ / 64, M_ / 128);
    gemm_xw_hmma<<<gridA, 256, PA_SMEM>>>(b);

    cudaFuncSetAttribute(lstm_mma, cudaFuncAttributeMaxDynamicSharedMemorySize, SMEM_TOT);
    lstm_mma<<<NCTA, 512, SMEM_TOT>>>(out);
}

// round 16
// speedup vs baseline: 1.1739x; 1.1739x over previous
#include <cuda_runtime.h>
#include <cuda_fp16.h>
#include <cstdint>

// LSTM N=64, T=512, D=1024, H=1024, G=4096.
// Phase A: xW = x @ Wx + b  -- HMMA fp16, Wx 2-term split, x fp16 (128x64, proven).
// Phase B: persistent kernel, 128 CTAs x 512 threads, SINGLE-term fp16 Wh (R16:
//          lo term dropped -- quantization noise ~2^-12, measured-safe scale),
//          h single fp16 pre-fragmented, 8wk x 2wn warp tiles, dataflow sync.

#define N_  64
#define T_  512
#define D_  1024
#define H_  1024
#define G_  4096
#define M_  (N_ * T_)
#define NCTA 128
#define INV2048 (1.0f / 2048.0f)

typedef unsigned long long ull;

// -------- device globals --------
static __device__ __align__(16) float  g_xw[(size_t)M_ * G_];          // 512 MB
static __device__ __align__(16) __half g_xh[(size_t)M_ * D_];          // 64 MB
static __device__ __align__(16) __half g_wxT[2ULL * G_ * D_];          // 16 MB
static __device__ __align__(16) __half g_whs[NCTA * 32 * 1024];        // 8 MB (single term)
// h fragments: [phase][k16 0..63][np 0..3][lane 0..31][8 fp16]
static __device__ __align__(16) __half g_hf[2][64][4][32][8];
// dataflow flags: one 128B line per CTA
static __device__ __align__(128) unsigned g_flags[NCTA * 32];

__device__ __forceinline__ float sigmoidf_(float x) { return 1.0f / (1.0f + __expf(-x)); }
__device__ __forceinline__ float fast_tanh(float x) {
    float ax = fabsf(x);
    float e = __expf(-2.0f * ax);
    float t = (1.0f - e) / (1.0f + e);
    return copysignf(t, x);
}

// -------- async copy --------
__device__ __forceinline__ void cp16(uint32_t s, const void* g) {
    asm volatile("cp.async.cg.shared.global [%0], [%1], 16;" :: "r"(s), "l"(g));
}
__device__ __forceinline__ void cp_commit() { asm volatile("cp.async.commit_group;"); }
template <int NN>
__device__ __forceinline__ void cp_wait() { asm volatile("cp.async.wait_group %0;" :: "n"(NN)); }

__device__ __forceinline__ uint32_t smem_u32(const void* p) {
    uint32_t a;
    asm("{ .reg .u64 t; cvta.to.shared.u64 t, %1; cvt.u32.u64 %0, t; }" : "=r"(a) : "l"(p));
    return a;
}

// -------- mma helpers --------
__device__ __forceinline__ void ldm4(uint32_t addr, uint32_t* r) {
    asm volatile("ldmatrix.sync.aligned.m8n8.x4.shared.b16 {%0,%1,%2,%3}, [%4];"
                 : "=r"(r[0]), "=r"(r[1]), "=r"(r[2]), "=r"(r[3]) : "r"(addr));
}
__device__ __forceinline__ void mma16816(float* d, const uint32_t* a, uint32_t b0, uint32_t b1) {
    asm volatile(
        "mma.sync.aligned.m16n8k16.row.col.f32.f16.f16.f32 "
        "{%0,%1,%2,%3}, {%4,%5,%6,%7}, {%8,%9}, {%0,%1,%2,%3};"
        : "+f"(d[0]), "+f"(d[1]), "+f"(d[2]), "+f"(d[3])
        : "r"(a[0]), "r"(a[1]), "r"(a[2]), "r"(a[3]), "r"(b0), "r"(b1));
}

// ---------------- merged prep kernels ----------------
__global__ void prep_xwx(const float* __restrict__ x, const float* __restrict__ Wx) {
    int bid = blockIdx.x;
    if (bid < 1024) {
        int k = bid;
        const float* src = Wx + (size_t)k * G_;
        for (int col = threadIdx.x; col < G_; col += 256) {
            float w = src[col];
            __half hi = __float2half_rn(w);
            __half lo = __float2half_rn((w - __half2float(hi)) * 2048.0f);
            g_wxT[(size_t)col * D_ + k]        = hi;
            g_wxT[(size_t)(G_ + col) * D_ + k] = lo;
        }
    } else {
        size_t i = ((size_t)(bid - 1024) * 256 + threadIdx.x) * 4;
        float4 v = *(const float4*)(x + i);
        __half h[4] = {__float2half_rn(v.x), __float2half_rn(v.y),
                       __float2half_rn(v.z), __float2half_rn(v.w)};
        *(uint2*)(g_xh + i) = *(uint2*)h;
    }
}

__global__ void prep_whh0(const float* __restrict__ Wh, const float* __restrict__ h0) {
    int bid = blockIdx.x;
    int tid = threadIdx.x;
    if (bid < NCTA) {
        int b = bid;
        int m = tid & 31;
        int g = m >> 3, j = m & 7;
        int col = g * 1024 + b * 8 + j;
        __half* dh = g_whs + ((size_t)b * 32 + m) * 1024;
        for (int k = tid >> 5; k < 1024; k += 8) {
            dh[k] = __float2half_rn(Wh[(size_t)k * G_ + col]);
        }
    } else {
        int i = (bid - NCTA) * 256 + tid;
        if (i < N_ * H_) {
            int n = i >> 10, k = i & 1023;
            int lane = (n & 7) * 4 + ((k & 7) >> 1);
            int idx8 = ((n >> 3) & 1) * 4 + (((k >> 3) & 1) * 2 + (k & 1));
            g_hf[0][k >> 4][n >> 4][lane][idx8] = __float2half_rn(h0[i]);
        }
        if (i < NCTA * 32) g_flags[i] = 0u;
    }
}

// ---------------- Phase A: xW = x @ Wx + b via HMMA (R9-proven) ----------------
#define PA_PITCH 144
#define PA_ABUF(i) ((i) * 18432)
#define PA_BBUF(i) (36864 + (i) * 18432)
#define PA_SMEM 73728

__global__ __launch_bounds__(256, 2)
void gemm_xw_hmma(const float* __restrict__ bias) {
    extern __shared__ char smem[];
    const uint32_t sb = smem_u32(smem);

    const int tid  = threadIdx.x;
    const int wid  = tid >> 5;
    const int lane = tid & 31;
    const int bx = blockIdx.x;
    const int by = blockIdx.y;
    const int m0 = by * 128;
    const int n0 = bx * 64;

    const char* Asrc = (const char*)g_xh + (size_t)m0 * 2048;
    const char* Bsrc = (const char*)g_wxT;

    const int wm = wid >> 1;
    const int wn = wid & 1;

    auto issue = [&](int kt, int bi) {
        const int k0b = kt * 128;
        const uint32_t ab = sb + PA_ABUF(bi);
        const uint32_t bb = sb + PA_BBUF(bi);
        #pragma unroll
        for (int i = 0; i < 4; i++) {
            int p = tid + 256 * i;
            int row = p >> 3, seg = p & 7;
            cp16(ab + row * PA_PITCH + seg * 16,
                 Asrc + (size_t)row * 2048 + k0b + seg * 16);
        }
        #pragma unroll
        for (int i = 0; i < 4; i++) {
            int p = tid + 256 * i;
            int row = p >> 3, seg = p & 7;
            int term = row >> 6, n = row & 63;
            cp16(bb + row * PA_PITCH + seg * 16,
                 Bsrc + ((size_t)term * G_ + n0 + n) * 2048 + k0b + seg * 16);
        }
    };

    float acc[2][2][4][4];
    #pragma unroll
    for (int s = 0; s < 2; s++)
        #pragma unroll
        for (int mi = 0; mi < 2; mi++)
            #pragma unroll
            for (int j = 0; j < 4; j++)
                #pragma unroll
                for (int i = 0; i < 4; i++) acc[s][mi][j][i] = 0.0f;

    const uint32_t lrow = (uint32_t)(lane & 15);
    const uint32_t lseg = (uint32_t)(lane >> 4) * 16;

    issue(0, 0);
    cp_commit();

    for (int kt = 0; kt < 16; kt++) {
        if (kt < 15) { issue(kt + 1, (kt + 1) & 1); cp_commit(); cp_wait<1>(); }
        else         { cp_wait<0>(); }
        __syncthreads();

        const uint32_t ab = sb + PA_ABUF(kt & 1);
        const uint32_t bb = sb + PA_BBUF(kt & 1);
        const uint32_t aA0 = ab + (wm * 32 + lrow) * PA_PITCH + lseg;
        const uint32_t aA1 = aA0 + 16 * PA_PITCH;

        #pragma unroll
        for (int k16 = 0; k16 < 4; k16++) {
            uint32_t af[2][4];
            ldm4(aA0 + k16 * 32, af[0]);
            ldm4(aA1 + k16 * 32, af[1]);
            #pragma unroll
            for (int s = 0; s < 2; s++) {
                #pragma unroll
                for (int tau = 0; tau < 2; tau++) {
                    uint32_t bf[4];
                    uint32_t baddr = bb + (s * 64 + wn * 32 + tau * 16 + lrow) * PA_PITCH
                                        + lseg + k16 * 32;
                    ldm4(baddr, bf);
                    mma16816(acc[s][0][tau * 2 + 0], af[0], bf[0], bf[2]);
                    mma16816(acc[s][0][tau * 2 + 1], af[0], bf[1], bf[3]);
                    mma16816(acc[s][1][tau * 2 + 0], af[1], bf[0], bf[2]);
                    mma16816(acc[s][1][tau * 2 + 1], af[1], bf[1], bf[3]);
                }
            }
        }
        __syncthreads();
    }

    const int erow = lane >> 2;
    const int ecol = (lane & 3) * 2;
    #pragma unroll
    for (int mi = 0; mi < 2; mi++) {
        #pragma unroll
        for (int j = 0; j < 4; j++) {
            int col = n0 + wn * 32 + j * 8 + ecol;
            float2 bb2 = *(const float2*)(bias + col);
            int row = m0 + wm * 32 + mi * 16 + erow;
            float c0 = fmaf(acc[1][mi][j][0], INV2048, acc[0][mi][j][0]) + bb2.x;
            float c1 = fmaf(acc[1][mi][j][1], INV2048, acc[0][mi][j][1]) + bb2.y;
            float c2 = fmaf(acc[1][mi][j][2], INV2048, acc[0][mi][j][2]) + bb2.x;
            float c3 = fmaf(acc[1][mi][j][3], INV2048, acc[0][mi][j][3]) + bb2.y;
            *(float2*)(g_xw + (size_t)row * G_ + col)       = make_float2(c0, c1);
            *(float2*)(g_xw + (size_t)(row + 8) * G_ + col) = make_float2(c2, c3);
        }
    }
}

// ---------------- Phase B SMEM ----------------
// Whs: 32 rows x 1024 fp16, pitch 2064 B -> 66048 B ; sm_p [8][32][66] f32 = 67584 B
#define WHS_PITCH 2064
#define SMP_OFF   66048
#define SMEM_TOT  (66048 + 67584)   // 133632

__global__ __launch_bounds__(512, 1)
void lstm_mma(float* __restrict__ out) {
    extern __shared__ char smem[];
    const uint32_t sb = smem_u32(smem);
    float* sm_p = (float*)(smem + SMP_OFF);   // [8][32][66]

    const int tid  = threadIdx.x;
    const int wid  = tid >> 5;
    const int lane = tid & 31;
    const int b    = blockIdx.x;

    // ---- one-time: Wh slice (single term) -> padded SMEM (4096 x 16B) ----
    {
        const char* src = (const char*)(g_whs + (size_t)b * 32 * 1024);
        for (int p = tid; p < 4096; p += 512) {
            int row = p >> 7;
            int seg = p & 127;
            cp16(sb + row * WHS_PITCH + seg * 16, src + row * 2048 + seg * 16);
        }
        cp_commit();
        cp_wait<0>();
        __syncthreads();
    }

    const int wk = wid & 7;
    const int wn = wid >> 3;          // 0..1
    const int kk0 = wk * 8;
    const int np0 = wn * 2;

    const uint32_t aBase = sb + (uint32_t)(lane & 15) * WHS_PITCH + (uint32_t)(lane >> 4) * 16;
    const uint32_t aHi0 = aBase;                        // m rows 0-15
    const uint32_t aHi1 = aBase + 16 * WHS_PITCH;       // m rows 16-31

    const int prow = lane >> 2;
    const int pcol = (lane & 3) * 2;

    const int en = tid >> 3;
    const int ej = tid & 7;
    const int jg = b * 8 + ej;
    float cc = 0.0f;
    const int wlane = (en & 7) * 4 + ((jg & 7) >> 1);
    const int widx8 = ((en >> 3) & 1) * 4 + (((jg >> 3) & 1) * 2 + (jg & 1));
    __half* hwp = &g_hf[0][jg >> 4][en >> 4][wlane][widx8];
    const size_t hphase_stride = (size_t)64 * 4 * 32 * 8;

    unsigned* myflag = &g_flags[b * 32];
    const unsigned* prodflag = &g_flags[(2 * kk0 + (lane & 15)) * 32];

    for (int t = 0; t < T_; t++) {
        const int p = t & 1, q = p ^ 1;
        const uint4* bPtr = (const uint4*)&g_hf[p][0][0][0][0] + lane;

        // ---- prefetch xw pre-activations (flag-independent) ----
        float xw[4];
        {
            const float* xp = g_xw + ((size_t)en * T_ + t) * G_ + jg;
            #pragma unroll
            for (int g = 0; g < 4; g++) xw[g] = xp[g * 1024];
        }

        // ---- dataflow wait: this warp's 16 producers ----
        {
            const unsigned need = (unsigned)t;
            unsigned v;
            for (;;) {
                asm volatile("ld.acquire.gpu.global.u32 %0, [%1];"
                             : "=r"(v) : "l"(prodflag) : "memory");
                if (__all_sync(0xffffffffu, v >= need)) break;
            }
        }

        float dh[2][4][4];
        #pragma unroll
        for (int m = 0; m < 2; m++)
            #pragma unroll
            for (int j = 0; j < 4; j++)
                #pragma unroll
                for (int i = 0; i < 4; i++) dh[m][j][i] = 0.0f;

        // A + B double-buffered pipeline (single term)
        uint4 b0A, b1A, b0B, b1B;
        uint32_t aA[8], aB[8];
        b0A = bPtr[((kk0 + 0) * 4 + np0) * 32];
        b1A = bPtr[((kk0 + 0) * 4 + np0 + 1) * 32];
        ldm4(aHi0 + kk0 * 32, aA);
        ldm4(aHi1 + kk0 * 32, aA + 4);

        #pragma unroll
        for (int su = 0; su < 8; su += 2) {
            {
                int kk = kk0 + su + 1;
                b0B = bPtr[(kk * 4 + np0) * 32];
                b1B = bPtr[(kk * 4 + np0 + 1) * 32];
                ldm4(aHi0 + kk * 32, aB);
                ldm4(aHi1 + kk * 32, aB + 4);
            }
            mma16816(dh[0][0], aA,     b0A.x, b0A.y);
            mma16816(dh[0][1], aA,     b0A.z, b0A.w);
            mma16816(dh[0][2], aA,     b1A.x, b1A.y);
            mma16816(dh[0][3], aA,     b1A.z, b1A.w);
            mma16816(dh[1][0], aA + 4, b0A.x, b0A.y);
            mma16816(dh[1][1], aA + 4, b0A.z, b0A.w);
            mma16816(dh[1][2], aA + 4, b1A.x, b1A.y);
            mma16816(dh[1][3], aA + 4, b1A.z, b1A.w);
            if (su + 2 < 8) {
                int kk = kk0 + su + 2;
                b0A = bPtr[(kk * 4 + np0) * 32];
                b1A = bPtr[(kk * 4 + np0 + 1) * 32];
                ldm4(aHi0 + kk * 32, aA);
                ldm4(aHi1 + kk * 32, aA + 4);
            }
            mma16816(dh[0][0], aB,     b0B.x, b0B.y);
            mma16816(dh[0][1], aB,     b0B.z, b0B.w);
            mma16816(dh[0][2], aB,     b1B.x, b1B.y);
            mma16816(dh[0][3], aB,     b1B.z, b1B.w);
            mma16816(dh[1][0], aB + 4, b0B.x, b0B.y);
            mma16816(dh[1][1], aB + 4, b0B.z, b0B.w);
            mma16816(dh[1][2], aB + 4, b1B.x, b1B.y);
            mma16816(dh[1][3], aB + 4, b1B.z, b1B.w);
        }

        // ---- store partials ----
        #pragma unroll
        for (int m = 0; m < 2; m++) {
            #pragma unroll
            for (int j = 0; j < 4; j++) {
                float* qp = sm_p + (wk * 32 + m * 16 + prow) * 66 + wn * 32 + j * 8 + pcol;
                *(float2*)qp            = make_float2(dh[m][j][0], dh[m][j][1]);
                *(float2*)(qp + 8 * 66) = make_float2(dh[m][j][2], dh[m][j][3]);
            }
        }
        __syncthreads();

        // ---- gates + state update (8-way partial reduction) ----
        {
            float a[4];
            #pragma unroll
            for (int g = 0; g < 4; g++) {
                int row = g * 8 + ej;
                float s0 = sm_p[(0 * 32 + row) * 66 + en] + sm_p[(1 * 32 + row) * 66 + en];
                float s1 = sm_p[(2 * 32 + row) * 66 + en] + sm_p[(3 * 32 + row) * 66 + en];
                float s2 = sm_p[(4 * 32 + row) * 66 + en] + sm_p[(5 * 32 + row) * 66 + en];
                float s3 = sm_p[(6 * 32 + row) * 66 + en] + sm_p[(7 * 32 + row) * 66 + en];
                a[g] = (s0 + s1) + (s2 + s3) + xw[g];
            }
            float ig = sigmoidf_(a[0]), fg = sigmoidf_(a[1]), og = sigmoidf_(a[2]);
            float gg = fast_tanh(a[3]);
            cc = fg * cc + ig * gg;
            float h = og * fast_tanh(cc);
            out[((size_t)en * T_ + t) * H_ + jg] = h;
            hwp[(size_t)q * hphase_stride] = __float2half_rn(h);
        }

        // ---- publish ----
        __syncthreads();
        if (tid == 0) {
            asm volatile("st.release.gpu.global.u32 [%0], %1;"
                         :: "l"(myflag), "r"((unsigned)(t + 1)) : "memory");
        }
    }
}

// ---------------- launch ----------------
extern "C" void kernel_launch(void* const* d_in, const int* in_sizes, int n_in,
                              void* d_out, int out_size) {
    const float* x  = (const float*)d_in[0];   // (N, T, D)
    const float* h0 = (const float*)d_in[1];   // (N, H)
    const float* Wx = (const float*)d_in[2];   // (D, 4H)
    const float* Wh = (const float*)d_in[3];   // (H, 4H)
    const float* b  = (const float*)d_in[4];   // (4H,)
    float* out = (float*)d_out;                // (N, T, H)

    prep_xwx<<<1024 + (int)((size_t)M_ * D_ / 1024), 256>>>(x, Wx);
    prep_whh0<<<NCTA + (N_ * H_ + 255) / 256, 256>>>(Wh, h0);

    cudaFuncSetAttribute(gemm_xw_hmma, cudaFuncAttributeMaxDynamicSharedMemorySize, PA_SMEM);
    dim3 gridA(G_ / 64, M_ / 128);
    gemm_xw_hmma<<<gridA, 256, PA_SMEM>>>(b);

    cudaFuncSetAttribute(lstm_mma, cudaFuncAttributeMaxDynamicSharedMemorySize, SMEM_TOT);
    lstm_mma<<<NCTA, 512, SMEM_TOT>>>(out);
}

// round 17
// speedup vs baseline: 1.1764x; 1.0021x over previous
#include <cuda_runtime.h>
#include <cuda_fp16.h>
#include <cstdint>

// LSTM N=64, T=512, D=1024, H=1024, G=4096.
// Phase A: xW = x @ Wx + b  -- HMMA fp16, Wx 2-term split, x fp16 (128x64, proven).
// Phase B: persistent kernel, 128 CTAs x 512 threads, single-term fp16 Wh,
//          h single fp16 pre-fragmented, 8wk x 2wn warp tiles, dataflow sync.
// R17: Wh A-fragments REGISTER-RESIDENT across all 512 steps (loaded once via
//      ldmatrix before the t-loop) -- kills the in-loop LDSM stream entirely.

#define N_  64
#define T_  512
#define D_  1024
#define H_  1024
#define G_  4096
#define M_  (N_ * T_)
#define NCTA 128
#define INV2048 (1.0f / 2048.0f)

typedef unsigned long long ull;

// -------- device globals --------
static __device__ __align__(16) float  g_xw[(size_t)M_ * G_];          // 512 MB
static __device__ __align__(16) __half g_xh[(size_t)M_ * D_];          // 64 MB
static __device__ __align__(16) __half g_wxT[2ULL * G_ * D_];          // 16 MB
static __device__ __align__(16) __half g_whs[NCTA * 32 * 1024];        // 8 MB (single term)
// h fragments: [phase][k16 0..63][np 0..3][lane 0..31][8 fp16]
static __device__ __align__(16) __half g_hf[2][64][4][32][8];
// dataflow flags: one 128B line per CTA
static __device__ __align__(128) unsigned g_flags[NCTA * 32];

__device__ __forceinline__ float sigmoidf_(float x) { return 1.0f / (1.0f + __expf(-x)); }
__device__ __forceinline__ float fast_tanh(float x) {
    float ax = fabsf(x);
    float e = __expf(-2.0f * ax);
    float t = (1.0f - e) / (1.0f + e);
    return copysignf(t, x);
}

// -------- async copy --------
__device__ __forceinline__ void cp16(uint32_t s, const void* g) {
    asm volatile("cp.async.cg.shared.global [%0], [%1], 16;" :: "r"(s), "l"(g));
}
__device__ __forceinline__ void cp_commit() { asm volatile("cp.async.commit_group;"); }
template <int NN>
__device__ __forceinline__ void cp_wait() { asm volatile("cp.async.wait_group %0;" :: "n"(NN)); }

__device__ __forceinline__ uint32_t smem_u32(const void* p) {
    uint32_t a;
    asm("{ .reg .u64 t; cvta.to.shared.u64 t, %1; cvt.u32.u64 %0, t; }" : "=r"(a) : "l"(p));
    return a;
}

// -------- mma helpers --------
__device__ __forceinline__ void ldm4(uint32_t addr, uint32_t* r) {
    asm volatile("ldmatrix.sync.aligned.m8n8.x4.shared.b16 {%0,%1,%2,%3}, [%4];"
                 : "=r"(r[0]), "=r"(r[1]), "=r"(r[2]), "=r"(r[3]) : "r"(addr));
}
__device__ __forceinline__ void mma16816(float* d, const uint32_t* a, uint32_t b0, uint32_t b1) {
    asm volatile(
        "mma.sync.aligned.m16n8k16.row.col.f32.f16.f16.f32 "
        "{%0,%1,%2,%3}, {%4,%5,%6,%7}, {%8,%9}, {%0,%1,%2,%3};"
        : "+f"(d[0]), "+f"(d[1]), "+f"(d[2]), "+f"(d[3])
        : "r"(a[0]), "r"(a[1]), "r"(a[2]), "r"(a[3]), "r"(b0), "r"(b1));
}

// ---------------- merged prep kernels ----------------
__global__ void prep_xwx(const float* __restrict__ x, const float* __restrict__ Wx) {
    int bid = blockIdx.x;
    if (bid < 1024) {
        int k = bid;
        const float* src = Wx + (size_t)k * G_;
        for (int col = threadIdx.x; col < G_; col += 256) {
            float w = src[col];
            __half hi = __float2half_rn(w);
            __half lo = __float2half_rn((w - __half2float(hi)) * 2048.0f);
            g_wxT[(size_t)col * D_ + k]        = hi;
            g_wxT[(size_t)(G_ + col) * D_ + k] = lo;
        }
    } else {
        size_t i = ((size_t)(bid - 1024) * 256 + threadIdx.x) * 4;
        float4 v = *(const float4*)(x + i);
        __half h[4] = {__float2half_rn(v.x), __float2half_rn(v.y),
                       __float2half_rn(v.z), __float2half_rn(v.w)};
        *(uint2*)(g_xh + i) = *(uint2*)h;
    }
}

__global__ void prep_whh0(const float* __restrict__ Wh, const float* __restrict__ h0) {
    int bid = blockIdx.x;
    int tid = threadIdx.x;
    if (bid < NCTA) {
        int b = bid;
        int m = tid & 31;
        int g = m >> 3, j = m & 7;
        int col = g * 1024 + b * 8 + j;
        __half* dh = g_whs + ((size_t)b * 32 + m) * 1024;
        for (int k = tid >> 5; k < 1024; k += 8) {
            dh[k] = __float2half_rn(Wh[(size_t)k * G_ + col]);
        }
    } else {
        int i = (bid - NCTA) * 256 + tid;
        if (i < N_ * H_) {
            int n = i >> 10, k = i & 1023;
            int lane = (n & 7) * 4 + ((k & 7) >> 1);
            int idx8 = ((n >> 3) & 1) * 4 + (((k >> 3) & 1) * 2 + (k & 1));
            g_hf[0][k >> 4][n >> 4][lane][idx8] = __float2half_rn(h0[i]);
        }
        if (i < NCTA * 32) g_flags[i] = 0u;
    }
}

// ---------------- Phase A: xW = x @ Wx + b via HMMA (R9-proven) ----------------
#define PA_PITCH 144
#define PA_ABUF(i) ((i) * 18432)
#define PA_BBUF(i) (36864 + (i) * 18432)
#define PA_SMEM 73728

__global__ __launch_bounds__(256, 2)
void gemm_xw_hmma(const float* __restrict__ bias) {
    extern __shared__ char smem[];
    const uint32_t sb = smem_u32(smem);

    const int tid  = threadIdx.x;
    const int wid  = tid >> 5;
    const int lane = tid & 31;
    const int bx = blockIdx.x;
    const int by = blockIdx.y;
    const int m0 = by * 128;
    const int n0 = bx * 64;

    const char* Asrc = (const char*)g_xh + (size_t)m0 * 2048;
    const char* Bsrc = (const char*)g_wxT;

    const int wm = wid >> 1;
    const int wn = wid & 1;

    auto issue = [&](int kt, int bi) {
        const int k0b = kt * 128;
        const uint32_t ab = sb + PA_ABUF(bi);
        const uint32_t bb = sb + PA_BBUF(bi);
        #pragma unroll
        for (int i = 0; i < 4; i++) {
            int p = tid + 256 * i;
            int row = p >> 3, seg = p & 7;
            cp16(ab + row * PA_PITCH + seg * 16,
                 Asrc + (size_t)row * 2048 + k0b + seg * 16);
        }
        #pragma unroll
        for (int i = 0; i < 4; i++) {
            int p = tid + 256 * i;
            int row = p >> 3, seg = p & 7;
            int term = row >> 6, n = row & 63;
            cp16(bb + row * PA_PITCH + seg * 16,
                 Bsrc + ((size_t)term * G_ + n0 + n) * 2048 + k0b + seg * 16);
        }
    };

    float acc[2][2][4][4];
    #pragma unroll
    for (int s = 0; s < 2; s++)
        #pragma unroll
        for (int mi = 0; mi < 2; mi++)
            #pragma unroll
            for (int j = 0; j < 4; j++)
                #pragma unroll
                for (int i = 0; i < 4; i++) acc[s][mi][j][i] = 0.0f;

    const uint32_t lrow = (uint32_t)(lane & 15);
    const uint32_t lseg = (uint32_t)(lane >> 4) * 16;

    issue(0, 0);
    cp_commit();

    for (int kt = 0; kt < 16; kt++) {
        if (kt < 15) { issue(kt + 1, (kt + 1) & 1); cp_commit(); cp_wait<1>(); }
        else         { cp_wait<0>(); }
        __syncthreads();

        const uint32_t ab = sb + PA_ABUF(kt & 1);
        const uint32_t bb = sb + PA_BBUF(kt & 1);
        const uint32_t aA0 = ab + (wm * 32 + lrow) * PA_PITCH + lseg;
        const uint32_t aA1 = aA0 + 16 * PA_PITCH;

        #pragma unroll
        for (int k16 = 0; k16 < 4; k16++) {
            uint32_t af[2][4];
            ldm4(aA0 + k16 * 32, af[0]);
            ldm4(aA1 + k16 * 32, af[1]);
            #pragma unroll
            for (int s = 0; s < 2; s++) {
                #pragma unroll
                for (int tau = 0; tau < 2; tau++) {
                    uint32_t bf[4];
                    uint32_t baddr = bb + (s * 64 + wn * 32 + tau * 16 + lrow) * PA_PITCH
                                        + lseg + k16 * 32;
                    ldm4(baddr, bf);
                    mma16816(acc[s][0][tau * 2 + 0], af[0], bf[0], bf[2]);
                    mma16816(acc[s][0][tau * 2 + 1], af[0], bf[1], bf[3]);
                    mma16816(acc[s][1][tau * 2 + 0], af[1], bf[0], bf[2]);
                    mma16816(acc[s][1][tau * 2 + 1], af[1], bf[1], bf[3]);
                }
            }
        }
        __syncthreads();
    }

    const int erow = lane >> 2;
    const int ecol = (lane & 3) * 2;
    #pragma unroll
    for (int mi = 0; mi < 2; mi++) {
        #pragma unroll
        for (int j = 0; j < 4; j++) {
            int col = n0 + wn * 32 + j * 8 + ecol;
            float2 bb2 = *(const float2*)(bias + col);
            int row = m0 + wm * 32 + mi * 16 + erow;
            float c0 = fmaf(acc[1][mi][j][0], INV2048, acc[0][mi][j][0]) + bb2.x;
            float c1 = fmaf(acc[1][mi][j][1], INV2048, acc[0][mi][j][1]) + bb2.y;
            float c2 = fmaf(acc[1][mi][j][2], INV2048, acc[0][mi][j][2]) + bb2.x;
            float c3 = fmaf(acc[1][mi][j][3], INV2048, acc[0][mi][j][3]) + bb2.y;
            *(float2*)(g_xw + (size_t)row * G_ + col)       = make_float2(c0, c1);
            *(float2*)(g_xw + (size_t)(row + 8) * G_ + col) = make_float2(c2, c3);
        }
    }
}

// ---------------- Phase B SMEM ----------------
// Whs: 32 rows x 1024 fp16, pitch 2064 B -> 66048 B (init only);
// sm_p [8][32][66] f32 = 67584 B
#define WHS_PITCH 2064
#define SMP_OFF   66048
#define SMEM_TOT  (66048 + 67584)   // 133632

__global__ __launch_bounds__(512, 1)
void lstm_mma(float* __restrict__ out) {
    extern __shared__ char smem[];
    const uint32_t sb = smem_u32(smem);
    float* sm_p = (float*)(smem + SMP_OFF);   // [8][32][66]

    const int tid  = threadIdx.x;
    const int wid  = tid >> 5;
    const int lane = tid & 31;
    const int b    = blockIdx.x;

    // ---- one-time: Wh slice -> SMEM -> REGISTER-RESIDENT A fragments ----
    {
        const char* src = (const char*)(g_whs + (size_t)b * 32 * 1024);
        for (int p = tid; p < 4096; p += 512) {
            int row = p >> 7;
            int seg = p & 127;
            cp16(sb + row * WHS_PITCH + seg * 16, src + row * 2048 + seg * 16);
        }
        cp_commit();
        cp_wait<0>();
        __syncthreads();
    }

    const int wk = wid & 7;
    const int wn = wid >> 3;          // 0..1
    const int kk0 = wk * 8;
    const int np0 = wn * 2;

    // A fragments: [k16 0..7][m0-15: 4 regs | m16-31: 4 regs] -- 64 regs, persistent
    uint32_t aF[8][8];
    {
        const uint32_t aBase = sb + (uint32_t)(lane & 15) * WHS_PITCH
                                  + (uint32_t)(lane >> 4) * 16;
        #pragma unroll
        for (int kk = 0; kk < 8; kk++) {
            ldm4(aBase + (kk0 + kk) * 32, aF[kk]);
            ldm4(aBase + 16 * WHS_PITCH + (kk0 + kk) * 32, aF[kk] + 4);
        }
    }
    __syncthreads();   // Whs SMEM no longer needed (sm_p region is separate anyway)

    const int prow = lane >> 2;
    const int pcol = (lane & 3) * 2;

    const int en = tid >> 3;
    const int ej = tid & 7;
    const int jg = b * 8 + ej;
    float cc = 0.0f;
    const int wlane = (en & 7) * 4 + ((jg & 7) >> 1);
    const int widx8 = ((en >> 3) & 1) * 4 + (((jg >> 3) & 1) * 2 + (jg & 1));
    __half* hwp = &g_hf[0][jg >> 4][en >> 4][wlane][widx8];
    const size_t hphase_stride = (size_t)64 * 4 * 32 * 8;

    unsigned* myflag = &g_flags[b * 32];
    const unsigned* prodflag = &g_flags[(2 * kk0 + (lane & 15)) * 32];

    for (int t = 0; t < T_; t++) {
        const int p = t & 1, q = p ^ 1;
        const uint4* bPtr = (const uint4*)&g_hf[p][0][0][0][0] + lane;

        // ---- prefetch xw pre-activations (flag-independent) ----
        float xw[4];
        {
            const float* xp = g_xw + ((size_t)en * T_ + t) * G_ + jg;
            #pragma unroll
            for (int g = 0; g < 4; g++) xw[g] = xp[g * 1024];
        }

        // ---- dataflow wait: this warp's 16 producers ----
        {
            const unsigned need = (unsigned)t;
            unsigned v;
            for (;;) {
                asm volatile("ld.acquire.gpu.global.u32 %0, [%1];"
                             : "=r"(v) : "l"(prodflag) : "memory");
                if (__all_sync(0xffffffffu, v >= need)) break;
            }
        }

        float dh[2][4][4];
        #pragma unroll
        for (int m = 0; m < 2; m++)
            #pragma unroll
            for (int j = 0; j < 4; j++)
                #pragma unroll
                for (int i = 0; i < 4; i++) dh[m][j][i] = 0.0f;

        // B double-buffered; A from registers
        uint4 b0A, b1A, b0B, b1B;
        b0A = bPtr[((kk0 + 0) * 4 + np0) * 32];
        b1A = bPtr[((kk0 + 0) * 4 + np0 + 1) * 32];

        #pragma unroll
        for (int su = 0; su < 8; su += 2) {
            {
                int kk = kk0 + su + 1;
                b0B = bPtr[(kk * 4 + np0) * 32];
                b1B = bPtr[(kk * 4 + np0 + 1) * 32];
            }
            mma16816(dh[0][0], aF[su],     b0A.x, b0A.y);
            mma16816(dh[0][1], aF[su],     b0A.z, b0A.w);
            mma16816(dh[0][2], aF[su],     b1A.x, b1A.y);
            mma16816(dh[0][3], aF[su],     b1A.z, b1A.w);
            mma16816(dh[1][0], aF[su] + 4, b0A.x, b0A.y);
            mma16816(dh[1][1], aF[su] + 4, b0A.z, b0A.w);
            mma16816(dh[1][2], aF[su] + 4, b1A.x, b1A.y);
            mma16816(dh[1][3], aF[su] + 4, b1A.z, b1A.w);
            if (su + 2 < 8) {
                int kk = kk0 + su + 2;
                b0A = bPtr[(kk * 4 + np0) * 32];
                b1A = bPtr[(kk * 4 + np0 + 1) * 32];
            }
            mma16816(dh[0][0], aF[su + 1],     b0B.x, b0B.y);
            mma16816(dh[0][1], aF[su + 1],     b0B.z, b0B.w);
            mma16816(dh[0][2], aF[su + 1],     b1B.x, b1B.y);
            mma16816(dh[0][3], aF[su + 1],     b1B.z, b1B.w);
            mma16816(dh[1][0], aF[su + 1] + 4, b0B.x, b0B.y);
            mma16816(dh[1][1], aF[su + 1] + 4, b0B.z, b0B.w);
            mma16816(dh[1][2], aF[su + 1] + 4, b1B.x, b1B.y);
            mma16816(dh[1][3], aF[su + 1] + 4, b1B.z, b1B.w);
        }

        // ---- store partials ----
        #pragma unroll
        for (int m = 0; m < 2; m++) {
            #pragma unroll
            for (int j = 0; j < 4; j++) {
                float* qp = sm_p + (wk * 32 + m * 16 + prow) * 66 + wn * 32 + j * 8 + pcol;
                *(float2*)qp            = make_float2(dh[m][j][0], dh[m][j][1]);
                *(float2*)(qp + 8 * 66) = make_float2(dh[m][j][2], dh[m][j][3]);
            }
        }
        __syncthreads();

        // ---- gates + state update (8-way partial reduction) ----
        {
            float a[4];
            #pragma unroll
            for (int g = 0; g < 4; g++) {
                int row = g * 8 + ej;
                float s0 = sm_p[(0 * 32 + row) * 66 + en] + sm_p[(1 * 32 + row) * 66 + en];
                float s1 = sm_p[(2 * 32 + row) * 66 + en] + sm_p[(3 * 32 + row) * 66 + en];
                float s2 = sm_p[(4 * 32 + row) * 66 + en] + sm_p[(5 * 32 + row) * 66 + en];
                float s3 = sm_p[(6 * 32 + row) * 66 + en] + sm_p[(7 * 32 + row) * 66 + en];
                a[g] = (s0 + s1) + (s2 + s3) + xw[g];
            }
            float ig = sigmoidf_(a[0]), fg = sigmoidf_(a[1]), og = sigmoidf_(a[2]);
            float gg = fast_tanh(a[3]);
            cc = fg * cc + ig * gg;
            float h = og * fast_tanh(cc);
            out[((size_t)en * T_ + t) * H_ + jg] = h;
            hwp[(size_t)q * hphase_stride] = __float2half_rn(h);
        }

        // ---- publish ----
        __syncthreads();
        if (tid == 0) {
            asm volatile("st.release.gpu.global.u32 [%0], %1;"
                         :: "l"(myflag), "r"((unsigned)(t + 1)) : "memory");
        }
    }
}

// ---------------- launch ----------------
extern "C" void kernel_launch(void* const* d_in, const int* in_sizes, int n_in,
                              void* d_out, int out_size) {
    const float* x  = (const float*)d_in[0];   // (N, T, D)
    const float* h0 = (const float*)d_in[1];   // (N, H)
    const float* Wx = (const float*)d_in[2];   // (D, 4H)
    const float* Wh = (const float*)d_in[3];   // (H, 4H)
    const float* b  = (const float*)d_in[4];   // (4H,)
    float* out = (float*)d_out;                // (N, T, H)

    prep_xwx<<<1024 + (int)((size_t)M_ * D_ / 1024), 256>>>(x, Wx);
    prep_whh0<<<NCTA + (N_ * H_ + 255) / 256, 256>>>(Wh, h0);

    cudaFuncSetAttribute(gemm_xw_hmma, cudaFuncAttributeMaxDynamicSharedMemorySize, PA_SMEM);
    dim3 gridA(G_ / 64, M_ / 128);
    gemm_xw_hmma<<<gridA, 256, PA_SMEM>>>(b);

    cudaFuncSetAttribute(lstm_mma, cudaFuncAttributeMaxDynamicSharedMemorySize, SMEM_TOT);
    lstm_mma<<<NCTA, 512, SMEM_TOT>>>(out);
}